// round 2
// baseline (speedup 1.0000x reference)
#include <cuda_runtime.h>
#include <cuda_bf16.h>
#include <cstdint>

// Problem constants
#define BB 8
#define TT 100
#define SS 400
#define KK 8
#define HH 512
#define VV 32000
#define MM (BB*TT)   // 800 rows

// ---------------- GEMM: logits = dec_out @ W + b  -> out (800 x 32000) ----------------
// Tile: BM=64, BN=128, BK=16, 256 threads, thread-tile 8x4.
#define BM 64
#define BN 128
#define BKD 16

__global__ __launch_bounds__(256)
void nmt_gemm_kernel(const float* __restrict__ A,     // (800, 512)
                     const float* __restrict__ Wm,    // (512, 32000)
                     const float* __restrict__ bias,  // (32000)
                     float* __restrict__ C)           // (800, 32000)
{
    __shared__ float As[BKD][BM];   // transposed A tile
    __shared__ float Bs[BKD][BN];

    const int bn = blockIdx.x;          // 0..249
    const int bm = blockIdx.y;          // 0..12
    const int tid = threadIdx.x;        // 0..255
    const int tn = tid & 31;            // 32 threads in N, 4 cols each
    const int tm = tid >> 5;            // 8 threads in M, 8 rows each

    const int row0 = bm * BM;
    const int col0 = bn * BN;

    // A load mapping: each thread loads one float4 (64 rows x 4 float4 per row)
    const int a_r = tid >> 2;           // 0..63
    const int a_c = tid & 3;            // 0..3  (float4 within BK=16)

    float acc[8][4];
#pragma unroll
    for (int i = 0; i < 8; i++)
#pragma unroll
        for (int j = 0; j < 4; j++) acc[i][j] = 0.f;

    for (int k0 = 0; k0 < HH; k0 += BKD) {
        // ---- load A tile (transposed into As[k][m]) ----
        float4 av = make_float4(0.f, 0.f, 0.f, 0.f);
        const int ar = row0 + a_r;
        if (ar < MM)
            av = *(const float4*)(A + (size_t)ar * HH + k0 + a_c * 4);
        As[a_c * 4 + 0][a_r] = av.x;
        As[a_c * 4 + 1][a_r] = av.y;
        As[a_c * 4 + 2][a_r] = av.z;
        As[a_c * 4 + 3][a_r] = av.w;

        // ---- load B tile: 16 x 128 floats = 512 float4, 2 per thread ----
#pragma unroll
        for (int j = 0; j < 2; j++) {
            const int idx = tid + j * 256;           // 0..511
            const int br = idx >> 5;                 // 0..15
            const int bc = (idx & 31) * 4;           // 0..124
            float4 bv = *(const float4*)(Wm + (size_t)(k0 + br) * VV + col0 + bc);
            *(float4*)&Bs[br][bc] = bv;
        }
        __syncthreads();

#pragma unroll
        for (int kk = 0; kk < BKD; kk++) {
            float a[8], bvals[4];
#pragma unroll
            for (int i = 0; i < 8; i++) a[i] = As[kk][tm * 8 + i];
#pragma unroll
            for (int j = 0; j < 4; j++) bvals[j] = Bs[kk][tn * 4 + j];
#pragma unroll
            for (int i = 0; i < 8; i++)
#pragma unroll
                for (int j = 0; j < 4; j++)
                    acc[i][j] = fmaf(a[i], bvals[j], acc[i][j]);
        }
        __syncthreads();
    }

    // ---- store with bias ----
    float bv[4];
#pragma unroll
    for (int j = 0; j < 4; j++) bv[j] = bias[col0 + tn * 4 + j];

#pragma unroll
    for (int i = 0; i < 8; i++) {
        const int r = row0 + tm * 8 + i;
        if (r < MM) {
            float* cp = C + (size_t)r * VV + col0 + tn * 4;
            float4 o;
            o.x = acc[i][0] + bv[0];
            o.y = acc[i][1] + bv[1];
            o.z = acc[i][2] + bv[2];
            o.w = acc[i][3] + bv[3];
            *(float4*)cp = o;
        }
    }
}

// ---------------- Finalize: per (b,t) row -> softmax + copy-dist blend + log ----------------
// One CTA per row. Dynamic smem holds the 32000-float scatter row (128 KB).
__global__ __launch_bounds__(1024)
void nmt_finalize_kernel(const float* __restrict__ weights,      // (B,T,S)
                         const float* __restrict__ p_trans,      // (B,T,1)
                         const float* __restrict__ trans_probs,  // (B,S,K)
                         const float* __restrict__ probs,        // (B,S,K)
                         const int* __restrict__ idxes,          // (B,S,K)  int32 (JAX x64 off)
                         float* __restrict__ out)                // (B,T,V) in: logits, out: result
{
    extern __shared__ float ts[];               // VV floats
    __shared__ float red_m[32];
    __shared__ float red_s[32];

    const int bt = blockIdx.x;                  // 0..799
    const int b = bt / TT;
    const int tid = threadIdx.x;
    float* row = out + (size_t)bt * VV;

    // zero scatter row
    for (int v = tid; v < VV; v += 1024) ts[v] = 0.f;
    __syncthreads();

    // scatter: ts[idx] += weights[b,t,s] * trans_probs[b,s,k] * (probs[b,s,k] > 0.05)
    const float* wrow = weights + (size_t)bt * SS;
    const float* pb   = probs + (size_t)b * SS * KK;
    const float* tpb  = trans_probs + (size_t)b * SS * KK;
    const int* ib     = idxes + (size_t)b * SS * KK;
    for (int i = tid; i < SS * KK; i += 1024) {
        const float pr = pb[i];
        if (pr > 0.05f) {
            const int s = i >> 3;               // KK = 8
            const float val = tpb[i] * wrow[s];
            const int vidx = ib[i];
            if (vidx >= 0 && vidx < VV)
                atomicAdd(&ts[vidx], val);
        }
    }

    // online (max, sumexp) over the logits row
    float m = -1e30f, ssum = 0.f;
    for (int v = tid; v < VV; v += 1024) {
        const float l = row[v];
        if (l > m) {
            ssum = ssum * __expf(m - l) + 1.f;
            m = l;
        } else {
            ssum += __expf(l - m);
        }
    }
    // warp reduce (m, s)
#pragma unroll
    for (int off = 16; off > 0; off >>= 1) {
        const float mo = __shfl_xor_sync(0xffffffffu, m, off);
        const float so = __shfl_xor_sync(0xffffffffu, ssum, off);
        const float mn = fmaxf(m, mo);
        ssum = ssum * __expf(m - mn) + so * __expf(mo - mn);
        m = mn;
    }
    const int wid = tid >> 5, lane = tid & 31;
    if (lane == 0) { red_m[wid] = m; red_s[wid] = ssum; }
    __syncthreads();   // also orders scatter atomics before final pass
    if (wid == 0) {
        float m2 = red_m[lane];
        float s2 = red_s[lane];
#pragma unroll
        for (int off = 16; off > 0; off >>= 1) {
            const float mo = __shfl_xor_sync(0xffffffffu, m2, off);
            const float so = __shfl_xor_sync(0xffffffffu, s2, off);
            const float mn = fmaxf(m2, mo);
            s2 = s2 * __expf(m2 - mn) + so * __expf(mo - mn);
            m2 = mn;
        }
        if (lane == 0) { red_m[0] = m2; red_s[0] = s2; }
    }
    __syncthreads();

    const float logZ = red_m[0] + __logf(red_s[0]);
    const float pt = p_trans[bt];
    const float lom = __logf(1.f - pt) - logZ;   // ts==0 fast path constant

    for (int v = tid; v < VV; v += 1024) {
        const float l = row[v];
        const float t = ts[v];
        float o;
        if (t == 0.f) {
            o = lom + l;                          // log((1-pt)*exp(l-logZ))
        } else {
            o = __logf(fmaf(pt, t, (1.f - pt) * __expf(l - logZ)));
        }
        row[v] = o;
    }
}

// ---------------- launch ----------------
extern "C" void kernel_launch(void* const* d_in, const int* in_sizes, int n_in,
                              void* d_out, int out_size)
{
    const float* dec_out     = (const float*)d_in[0];
    const float* W           = (const float*)d_in[1];
    const float* bias        = (const float*)d_in[2];
    const float* weights     = (const float*)d_in[3];
    const float* p_trans     = (const float*)d_in[4];
    const float* trans_probs = (const float*)d_in[5];
    const float* probs       = (const float*)d_in[6];
    const int*   idxes       = (const int*)d_in[7];
    float* out = (float*)d_out;

    dim3 grid(VV / BN, (MM + BM - 1) / BM);   // (250, 13)
    nmt_gemm_kernel<<<grid, 256>>>(dec_out, W, bias, out);

    const int smem = VV * sizeof(float);      // 128000 bytes
    cudaFuncSetAttribute(nmt_finalize_kernel,
                         cudaFuncAttributeMaxDynamicSharedMemorySize, smem);
    nmt_finalize_kernel<<<MM, 1024, smem>>>(weights, p_trans, trans_probs, probs, idxes, out);
}

// round 4
// speedup vs baseline: 1.6928x; 1.6928x over previous
#include <cuda_runtime.h>
#include <cuda_bf16.h>
#include <cstdint>

// ---------------- problem constants ----------------
#define BB 8
#define TT 100
#define SS 400
#define KK 8
#define HH 512
#define VV 32000
#define MMROWS 800

// ---------------- extended-K bf16 operands ----------------
// A2: [896][1536]  cols [0:512)=A_hi [512:1024)=A_hi [1024:1536)=A_lo
// B2: [1536][32000] rows [0:512)=W_hi [512:1024)=W_lo [1024:1536)=W_hi
// => A2@B2 = Ah*Wh + Ah*Wl + Al*Wh  (drops Al*Wl ~ 2^-18 rel)
#define KEXT 1536
#define MPAD 896
__device__ __nv_bfloat16 d_A2[(size_t)MPAD * KEXT];            // 2.75 MB (zero-init pads rows 800..895)
__device__ __nv_bfloat16 d_B2[(size_t)KEXT * VV];              // 98.3 MB

static __device__ __forceinline__ uint32_t pack_bf2(__nv_bfloat16 a, __nv_bfloat16 b) {
    return (uint32_t)__bfloat16_as_ushort(a) | ((uint32_t)__bfloat16_as_ushort(b) << 16);
}

// ---------------- conversion: A -> A2 ----------------
__global__ __launch_bounds__(256)
void conv_a_kernel(const float* __restrict__ A) {
    const int idx = blockIdx.x * 256 + threadIdx.x;      // 800*128 threads
    if (idx >= MMROWS * 128) return;
    const int row = idx >> 7;
    const int kq = idx & 127;                            // float4 index within 512
    const float4 v = *(const float4*)(A + (size_t)row * HH + kq * 4);
    const float e[4] = {v.x, v.y, v.z, v.w};
    __nv_bfloat16 h[4], l[4];
#pragma unroll
    for (int j = 0; j < 4; j++) {
        h[j] = __float2bfloat16(e[j]);
        l[j] = __float2bfloat16(e[j] - __bfloat162float(h[j]));
    }
    uint2 hp, lp;
    hp.x = pack_bf2(h[0], h[1]); hp.y = pack_bf2(h[2], h[3]);
    lp.x = pack_bf2(l[0], l[1]); lp.y = pack_bf2(l[2], l[3]);
    __nv_bfloat16* base = d_A2 + (size_t)row * KEXT;
    *(uint2*)(base + kq * 4)        = hp;
    *(uint2*)(base + 512 + kq * 4)  = hp;
    *(uint2*)(base + 1024 + kq * 4) = lp;
}

// ---------------- conversion: W -> B2 ----------------
__global__ __launch_bounds__(256)
void conv_b_kernel(const float* __restrict__ W) {
    const int idx = blockIdx.x * 256 + threadIdx.x;      // 512*8000 threads
    if (idx >= HH * (VV / 4)) return;
    const int k = idx / (VV / 4);
    const int vq = idx % (VV / 4);
    const float4 v = *(const float4*)(W + (size_t)k * VV + vq * 4);
    const float e[4] = {v.x, v.y, v.z, v.w};
    __nv_bfloat16 h[4], l[4];
#pragma unroll
    for (int j = 0; j < 4; j++) {
        h[j] = __float2bfloat16(e[j]);
        l[j] = __float2bfloat16(e[j] - __bfloat162float(h[j]));
    }
    uint2 hp, lp;
    hp.x = pack_bf2(h[0], h[1]); hp.y = pack_bf2(h[2], h[3]);
    lp.x = pack_bf2(l[0], l[1]); lp.y = pack_bf2(l[2], l[3]);
    *(uint2*)(d_B2 + (size_t)k * VV + vq * 4)          = hp;   // W_hi
    *(uint2*)(d_B2 + (size_t)(k + 512) * VV + vq * 4)  = lp;   // W_lo
    *(uint2*)(d_B2 + (size_t)(k + 1024) * VV + vq * 4) = hp;   // W_hi
}

// ---------------- mma.sync GEMM ----------------
#define BM 128
#define BN 128
#define BK 32
#define STAGES 4
#define KTILES (KEXT / BK)          // 48
#define A_STRIDE 40                  // bf16 elems/row (32 + 8 pad) -> 80 B
#define B_STRIDE 136                 // bf16 elems/row (128 + 8 pad) -> 272 B
#define A_BYTES (BM * A_STRIDE * 2)  // 10240
#define B_BYTES (BK * B_STRIDE * 2)  // 8704
#define STAGE_BYTES (A_BYTES + B_BYTES)  // 18944
#define GEMM_SMEM (STAGES * STAGE_BYTES) // 75776

__device__ __forceinline__ uint32_t smem_u32(const void* p) {
    uint32_t a;
    asm("{ .reg .u64 t; cvta.to.shared.u64 t, %1; cvt.u32.u64 %0, t; }" : "=r"(a) : "l"(p));
    return a;
}
__device__ __forceinline__ void cp16(uint32_t dst, const void* src) {
    asm volatile("cp.async.cg.shared.global [%0], [%1], 16;" :: "r"(dst), "l"(src) : "memory");
}
__device__ __forceinline__ void cp_commit() {
    asm volatile("cp.async.commit_group;" ::: "memory");
}
__device__ __forceinline__ void cp_wait2() {
    asm volatile("cp.async.wait_group 2;" ::: "memory");
}
__device__ __forceinline__ void ldm_x4(uint32_t* r, uint32_t addr) {
    asm volatile("ldmatrix.sync.aligned.m8n8.x4.shared.b16 {%0,%1,%2,%3}, [%4];"
                 : "=r"(r[0]), "=r"(r[1]), "=r"(r[2]), "=r"(r[3]) : "r"(addr));
}
__device__ __forceinline__ void ldm_x4_t(uint32_t* r, uint32_t addr) {
    asm volatile("ldmatrix.sync.aligned.m8n8.x4.trans.shared.b16 {%0,%1,%2,%3}, [%4];"
                 : "=r"(r[0]), "=r"(r[1]), "=r"(r[2]), "=r"(r[3]) : "r"(addr));
}
__device__ __forceinline__ void mma16816(float* c, const uint32_t* a, uint32_t b0, uint32_t b1) {
    asm volatile(
        "mma.sync.aligned.m16n8k16.row.col.f32.bf16.bf16.f32 "
        "{%0,%1,%2,%3}, {%4,%5,%6,%7}, {%8,%9}, {%0,%1,%2,%3};"
        : "+f"(c[0]), "+f"(c[1]), "+f"(c[2]), "+f"(c[3])
        : "r"(a[0]), "r"(a[1]), "r"(a[2]), "r"(a[3]), "r"(b0), "r"(b1));
}

__global__ __launch_bounds__(256)
void nmt_gemm_mma(const float* __restrict__ bias, float* __restrict__ C) {
    extern __shared__ char sm[];
    const uint32_t sm_base = smem_u32(sm);
    const int tid = threadIdx.x;
    const int warp = tid >> 5, lane = tid & 31;
    const int warp_m = warp >> 2;         // 0..1 -> 64 rows
    const int warp_n = warp & 3;          // 0..3 -> 32 cols
    const int nt = blockIdx.x;            // 0..249
    const int mt = blockIdx.y;            // 0..6

    const __nv_bfloat16* Ag = d_A2 + (size_t)mt * BM * KEXT;
    const __nv_bfloat16* Bg = d_B2 + (size_t)nt * BN;

    // per-thread load coords (2 chunks each for A and B per stage)
    const int a_row0 = tid >> 2;                  // then +64
    const int a_q = tid & 3;
    const int b_row0 = tid >> 4;                  // then +16
    const int b_q = tid & 15;

    float acc[4][4][4];
#pragma unroll
    for (int t = 0; t < 4; t++)
#pragma unroll
        for (int n = 0; n < 4; n++)
#pragma unroll
            for (int j = 0; j < 4; j++) acc[t][n][j] = 0.f;

    auto load_stage = [&](int s, int kb) {
        const uint32_t as = sm_base + s * STAGE_BYTES;
        const uint32_t bs = as + A_BYTES;
#pragma unroll
        for (int j = 0; j < 2; j++) {
            const int row = a_row0 + j * 64;
            cp16(as + row * 80 + a_q * 16,
                 Ag + (size_t)row * KEXT + kb * BK + a_q * 8);
        }
#pragma unroll
        for (int j = 0; j < 2; j++) {
            const int row = b_row0 + j * 16;
            cp16(bs + row * 272 + b_q * 16,
                 Bg + (size_t)(kb * BK + row) * VV + b_q * 8);
        }
    };

    // prologue
#pragma unroll
    for (int s = 0; s < STAGES - 1; s++) { load_stage(s, s); cp_commit(); }

    for (int it = 0; it < KTILES; it++) {
        cp_wait2();
        __syncthreads();
        if (it + STAGES - 1 < KTILES) load_stage((it + STAGES - 1) & (STAGES - 1), it + STAGES - 1);
        cp_commit();

        const uint32_t as = sm_base + (it & (STAGES - 1)) * STAGE_BYTES;
        const uint32_t bs = as + A_BYTES;
#pragma unroll
        for (int k2 = 0; k2 < 2; k2++) {
            uint32_t af[4][4];
#pragma unroll
            for (int t = 0; t < 4; t++)
                ldm_x4(af[t], as + (warp_m * 64 + t * 16 + (lane & 15)) * 80
                              + k2 * 32 + (lane >> 4) * 16);
            uint32_t bf[2][4];
#pragma unroll
            for (int p = 0; p < 2; p++)
                ldm_x4_t(bf[p], bs + (k2 * 16 + (lane & 15)) * 272
                               + (warp_n * 32 + p * 16 + (lane >> 4) * 8) * 2);
#pragma unroll
            for (int t = 0; t < 4; t++)
#pragma unroll
                for (int n = 0; n < 4; n++)
                    mma16816(acc[t][n], af[t], bf[n >> 1][(n & 1) * 2], bf[n >> 1][(n & 1) * 2 + 1]);
        }
    }

    // epilogue: add bias, store (guard M)
    const int group = lane >> 2, tg = lane & 3;
#pragma unroll
    for (int t = 0; t < 4; t++) {
        const int r0 = mt * BM + warp_m * 64 + t * 16 + group;
        const int r1 = r0 + 8;
#pragma unroll
        for (int n = 0; n < 4; n++) {
            const int col = nt * BN + warp_n * 32 + n * 8 + tg * 2;
            const float2 bv = *(const float2*)(bias + col);
            if (r0 < MMROWS) {
                float2 o; o.x = acc[t][n][0] + bv.x; o.y = acc[t][n][1] + bv.y;
                *(float2*)(C + (size_t)r0 * VV + col) = o;
            }
            if (r1 < MMROWS) {
                float2 o; o.x = acc[t][n][2] + bv.x; o.y = acc[t][n][3] + bv.y;
                *(float2*)(C + (size_t)r1 * VV + col) = o;
            }
        }
    }
}

// ---------------- Finalize: per (b,t) row -> scatter + softmax + blend + log ----------------
__global__ __launch_bounds__(1024)
void nmt_finalize_kernel(const float* __restrict__ weights,
                         const float* __restrict__ p_trans,
                         const float* __restrict__ trans_probs,
                         const float* __restrict__ probs,
                         const int* __restrict__ idxes,
                         float* __restrict__ out) {
    extern __shared__ float ts[];               // VV floats
    __shared__ float red_m[32];
    __shared__ float red_s[32];

    const int bt = blockIdx.x;
    const int b = bt / TT;
    const int tid = threadIdx.x;
    float* row = out + (size_t)bt * VV;
    float4* tsv = (float4*)ts;

    const float4 z4 = make_float4(0.f, 0.f, 0.f, 0.f);
    for (int v = tid; v < VV / 4; v += 1024) tsv[v] = z4;
    __syncthreads();

    const float* wrow = weights + (size_t)bt * SS;
    const float* pb   = probs + (size_t)b * SS * KK;
    const float* tpb  = trans_probs + (size_t)b * SS * KK;
    const int* ib     = idxes + (size_t)b * SS * KK;
    for (int i = tid; i < SS * KK; i += 1024) {
        const float pr = pb[i];
        if (pr > 0.05f) {
            const float val = tpb[i] * wrow[i >> 3];
            const int vidx = ib[i];
            if (vidx >= 0 && vidx < VV) atomicAdd(&ts[vidx], val);
        }
    }

    float m = -1e30f, ssum = 0.f;
    const float4* rowv = (const float4*)row;
    for (int i = tid; i < VV / 4; i += 1024) {
        const float4 l = rowv[i];
        const float e[4] = {l.x, l.y, l.z, l.w};
#pragma unroll
        for (int j = 0; j < 4; j++) {
            const float v = e[j];
            if (v > m) { ssum = ssum * __expf(m - v) + 1.f; m = v; }
            else       { ssum += __expf(v - m); }
        }
    }
#pragma unroll
    for (int off = 16; off > 0; off >>= 1) {
        const float mo = __shfl_xor_sync(0xffffffffu, m, off);
        const float so = __shfl_xor_sync(0xffffffffu, ssum, off);
        const float mn = fmaxf(m, mo);
        ssum = ssum * __expf(m - mn) + so * __expf(mo - mn);
        m = mn;
    }
    const int wid = tid >> 5, lane = tid & 31;
    if (lane == 0) { red_m[wid] = m; red_s[wid] = ssum; }
    __syncthreads();   // also orders scatter atomics
    if (wid == 0) {
        float m2 = red_m[lane];
        float s2 = red_s[lane];
#pragma unroll
        for (int off = 16; off > 0; off >>= 1) {
            const float mo = __shfl_xor_sync(0xffffffffu, m2, off);
            const float so = __shfl_xor_sync(0xffffffffu, s2, off);
            const float mn = fmaxf(m2, mo);
            s2 = s2 * __expf(m2 - mn) + so * __expf(mo - mn);
            m2 = mn;
        }
        if (lane == 0) { red_m[0] = m2; red_s[0] = s2; }
    }
    __syncthreads();

    const float logZ = red_m[0] + __logf(red_s[0]);
    const float pt = p_trans[bt];
    const float lom = __logf(1.f - pt) - logZ;

    float4* rowv_w = (float4*)row;
    for (int i = tid; i < VV / 4; i += 1024) {
        const float4 l = rowv_w[i];
        const float4 t = tsv[i];
        const float le[4] = {l.x, l.y, l.z, l.w};
        const float te[4] = {t.x, t.y, t.z, t.w};
        float oe[4];
#pragma unroll
        for (int j = 0; j < 4; j++) {
            if (te[j] == 0.f) oe[j] = lom + le[j];
            else oe[j] = __logf(fmaf(pt, te[j], (1.f - pt) * __expf(le[j] - logZ)));
        }
        rowv_w[i] = make_float4(oe[0], oe[1], oe[2], oe[3]);
    }
}

// ---------------- launch ----------------
extern "C" void kernel_launch(void* const* d_in, const int* in_sizes, int n_in,
                              void* d_out, int out_size) {
    const float* dec_out     = (const float*)d_in[0];
    const float* W           = (const float*)d_in[1];
    const float* bias        = (const float*)d_in[2];
    const float* weights     = (const float*)d_in[3];
    const float* p_trans     = (const float*)d_in[4];
    const float* trans_probs = (const float*)d_in[5];
    const float* probs       = (const float*)d_in[6];
    const int*   idxes       = (const int*)d_in[7];
    float* out = (float*)d_out;

    conv_a_kernel<<<(MMROWS * 128 + 255) / 256, 256>>>(dec_out);
    conv_b_kernel<<<(HH * (VV / 4) + 255) / 256, 256>>>(W);

    cudaFuncSetAttribute(nmt_gemm_mma, cudaFuncAttributeMaxDynamicSharedMemorySize, GEMM_SMEM);
    nmt_gemm_mma<<<dim3(VV / BN, MPAD / BM), 256, GEMM_SMEM>>>(bias, out);

    const int fin_smem = VV * sizeof(float);
    cudaFuncSetAttribute(nmt_finalize_kernel, cudaFuncAttributeMaxDynamicSharedMemorySize, fin_smem);
    nmt_finalize_kernel<<<MMROWS, 1024, fin_smem>>>(weights, p_trans, trans_probs, probs, idxes, out);
}

// round 5
// speedup vs baseline: 2.1084x; 1.2455x over previous
#include <cuda_runtime.h>
#include <cuda_fp16.h>
#include <cstdint>

// ---------------- problem constants ----------------
#define BB 8
#define TT 100
#define SS 400
#define KK 8
#define HH 512
#define VV 32000
#define MMROWS 800
#define MPAD 896

// fp16 operands (single GEMM, K=512; fp16's 11-bit mantissa keeps
// logit error ~2e-4 abs -> rel err ~1e-4, under the 1e-3 threshold)
__device__ __half d_A2[(size_t)MPAD * HH];     // 0.92 MB (pad rows stay zero-init)
__device__ __half d_B2[(size_t)HH * VV];       // 32.8 MB (fits in L2)

static __device__ __forceinline__ uint32_t pack_h2(__half a, __half b) {
    return (uint32_t)__half_as_ushort(a) | ((uint32_t)__half_as_ushort(b) << 16);
}

// ---------------- conversion: A -> fp16 ----------------
__global__ __launch_bounds__(256)
void conv_a_kernel(const float* __restrict__ A) {
    const int idx = blockIdx.x * 256 + threadIdx.x;      // 800*128
    if (idx >= MMROWS * 128) return;
    const int row = idx >> 7;
    const int kq = idx & 127;
    const float4 v = *(const float4*)(A + (size_t)row * HH + kq * 4);
    uint2 p;
    p.x = pack_h2(__float2half_rn(v.x), __float2half_rn(v.y));
    p.y = pack_h2(__float2half_rn(v.z), __float2half_rn(v.w));
    *(uint2*)(d_A2 + (size_t)row * HH + kq * 4) = p;
}

// ---------------- conversion: W -> fp16 ----------------
__global__ __launch_bounds__(256)
void conv_b_kernel(const float* __restrict__ W) {
    const int idx = blockIdx.x * 256 + threadIdx.x;      // 512*8000
    if (idx >= HH * (VV / 4)) return;
    const float4 v = *(const float4*)(W + (size_t)idx * 4);
    uint2 p;
    p.x = pack_h2(__float2half_rn(v.x), __float2half_rn(v.y));
    p.y = pack_h2(__float2half_rn(v.z), __float2half_rn(v.w));
    *(uint2*)(d_B2 + (size_t)idx * 4) = p;
}

// ---------------- mma.sync GEMM ----------------
#define BM 128
#define BN 128
#define BK 32
#define STAGES 4
#define KTILES (HH / BK)             // 16
#define A_STRIDE 40                  // halves/row (32 + 8 pad) -> 80 B
#define B_STRIDE 136                 // halves/row (128 + 8 pad) -> 272 B
#define A_BYTES (BM * A_STRIDE * 2)  // 10240
#define B_BYTES (BK * B_STRIDE * 2)  // 8704
#define STAGE_BYTES (A_BYTES + B_BYTES)  // 18944
#define GEMM_SMEM (STAGES * STAGE_BYTES) // 75776

__device__ __forceinline__ uint32_t smem_u32(const void* p) {
    uint32_t a;
    asm("{ .reg .u64 t; cvta.to.shared.u64 t, %1; cvt.u32.u64 %0, t; }" : "=r"(a) : "l"(p));
    return a;
}
__device__ __forceinline__ void cp16(uint32_t dst, const void* src) {
    asm volatile("cp.async.cg.shared.global [%0], [%1], 16;" :: "r"(dst), "l"(src) : "memory");
}
__device__ __forceinline__ void cp_commit() {
    asm volatile("cp.async.commit_group;" ::: "memory");
}
__device__ __forceinline__ void cp_wait2() {
    asm volatile("cp.async.wait_group 2;" ::: "memory");
}
__device__ __forceinline__ void ldm_x4(uint32_t* r, uint32_t addr) {
    asm volatile("ldmatrix.sync.aligned.m8n8.x4.shared.b16 {%0,%1,%2,%3}, [%4];"
                 : "=r"(r[0]), "=r"(r[1]), "=r"(r[2]), "=r"(r[3]) : "r"(addr));
}
__device__ __forceinline__ void ldm_x4_t(uint32_t* r, uint32_t addr) {
    asm volatile("ldmatrix.sync.aligned.m8n8.x4.trans.shared.b16 {%0,%1,%2,%3}, [%4];"
                 : "=r"(r[0]), "=r"(r[1]), "=r"(r[2]), "=r"(r[3]) : "r"(addr));
}
__device__ __forceinline__ void mma16816(float* c, const uint32_t* a, uint32_t b0, uint32_t b1) {
    asm volatile(
        "mma.sync.aligned.m16n8k16.row.col.f32.f16.f16.f32 "
        "{%0,%1,%2,%3}, {%4,%5,%6,%7}, {%8,%9}, {%0,%1,%2,%3};"
        : "+f"(c[0]), "+f"(c[1]), "+f"(c[2]), "+f"(c[3])
        : "r"(a[0]), "r"(a[1]), "r"(a[2]), "r"(a[3]), "r"(b0), "r"(b1));
}

__global__ __launch_bounds__(256)
void nmt_gemm_mma(const float* __restrict__ bias, float* __restrict__ C) {
    extern __shared__ char sm[];
    const uint32_t sm_base = smem_u32(sm);
    const int tid = threadIdx.x;
    const int warp = tid >> 5, lane = tid & 31;
    const int warp_m = warp >> 2;         // 0..1 -> 64 rows
    const int warp_n = warp & 3;          // 0..3 -> 32 cols
    const int nt = blockIdx.x;            // 0..249
    const int mt = blockIdx.y;            // 0..6

    const __half* Ag = d_A2 + (size_t)mt * BM * HH;
    const __half* Bg = d_B2 + (size_t)nt * BN;

    const int a_row0 = tid >> 2;
    const int a_q = tid & 3;
    const int b_row0 = tid >> 4;
    const int b_q = tid & 15;

    float acc[4][4][4];
#pragma unroll
    for (int t = 0; t < 4; t++)
#pragma unroll
        for (int n = 0; n < 4; n++)
#pragma unroll
            for (int j = 0; j < 4; j++) acc[t][n][j] = 0.f;

    auto load_stage = [&](int s, int kb) {
        const uint32_t as = sm_base + s * STAGE_BYTES;
        const uint32_t bs = as + A_BYTES;
#pragma unroll
        for (int j = 0; j < 2; j++) {
            const int row = a_row0 + j * 64;
            cp16(as + row * 80 + a_q * 16,
                 Ag + (size_t)row * HH + kb * BK + a_q * 8);
        }
#pragma unroll
        for (int j = 0; j < 2; j++) {
            const int row = b_row0 + j * 16;
            cp16(bs + row * 272 + b_q * 16,
                 Bg + (size_t)(kb * BK + row) * VV + b_q * 8);
        }
    };

#pragma unroll
    for (int s = 0; s < STAGES - 1; s++) { load_stage(s, s); cp_commit(); }

    for (int it = 0; it < KTILES; it++) {
        cp_wait2();
        __syncthreads();
        if (it + STAGES - 1 < KTILES) load_stage((it + STAGES - 1) & (STAGES - 1), it + STAGES - 1);
        cp_commit();

        const uint32_t as = sm_base + (it & (STAGES - 1)) * STAGE_BYTES;
        const uint32_t bs = as + A_BYTES;
#pragma unroll
        for (int k2 = 0; k2 < 2; k2++) {
            uint32_t af[4][4];
#pragma unroll
            for (int t = 0; t < 4; t++)
                ldm_x4(af[t], as + (warp_m * 64 + t * 16 + (lane & 15)) * 80
                              + k2 * 32 + (lane >> 4) * 16);
            uint32_t bf[2][4];
#pragma unroll
            for (int p = 0; p < 2; p++)
                ldm_x4_t(bf[p], bs + (k2 * 16 + (lane & 15)) * 272
                               + (warp_n * 32 + p * 16 + (lane >> 4) * 8) * 2);
#pragma unroll
            for (int t = 0; t < 4; t++)
#pragma unroll
                for (int n = 0; n < 4; n++)
                    mma16816(acc[t][n], af[t], bf[n >> 1][(n & 1) * 2], bf[n >> 1][(n & 1) * 2 + 1]);
        }
    }

    const int group = lane >> 2, tg = lane & 3;
#pragma unroll
    for (int t = 0; t < 4; t++) {
        const int r0 = mt * BM + warp_m * 64 + t * 16 + group;
        const int r1 = r0 + 8;
#pragma unroll
        for (int n = 0; n < 4; n++) {
            const int col = nt * BN + warp_n * 32 + n * 8 + tg * 2;
            const float2 bv = *(const float2*)(bias + col);
            if (r0 < MMROWS) {
                float2 o; o.x = acc[t][n][0] + bv.x; o.y = acc[t][n][1] + bv.y;
                *(float2*)(C + (size_t)r0 * VV + col) = o;
            }
            if (r1 < MMROWS) {
                float2 o; o.x = acc[t][n][2] + bv.x; o.y = acc[t][n][3] + bv.y;
                *(float2*)(C + (size_t)r1 * VV + col) = o;
            }
        }
    }
}

// ---------------- Finalize: per (b,t) row -> scatter + softmax + blend + log ----------------
__global__ __launch_bounds__(1024)
void nmt_finalize_kernel(const float* __restrict__ weights,
                         const float* __restrict__ p_trans,
                         const float* __restrict__ trans_probs,
                         const float* __restrict__ probs,
                         const int* __restrict__ idxes,
                         float* __restrict__ out) {
    extern __shared__ float ts[];               // VV floats
    __shared__ float red_m[32];
    __shared__ float red_s[32];

    const int bt = blockIdx.x;
    const int b = bt / TT;
    const int tid = threadIdx.x;
    float* row = out + (size_t)bt * VV;
    float4* tsv = (float4*)ts;

    const float4 z4 = make_float4(0.f, 0.f, 0.f, 0.f);
    for (int v = tid; v < VV / 4; v += 1024) tsv[v] = z4;
    __syncthreads();

    const float* wrow = weights + (size_t)bt * SS;
    const float* pb   = probs + (size_t)b * SS * KK;
    const float* tpb  = trans_probs + (size_t)b * SS * KK;
    const int* ib     = idxes + (size_t)b * SS * KK;
    for (int i = tid; i < SS * KK; i += 1024) {
        const float pr = pb[i];
        if (pr > 0.05f) {
            const float val = tpb[i] * wrow[i >> 3];
            const int vidx = ib[i];
            if (vidx >= 0 && vidx < VV) atomicAdd(&ts[vidx], val);
        }
    }

    float m = -1e30f, ssum = 0.f;
    const float4* rowv = (const float4*)row;
    for (int i = tid; i < VV / 4; i += 1024) {
        const float4 l = rowv[i];
        const float e[4] = {l.x, l.y, l.z, l.w};
#pragma unroll
        for (int j = 0; j < 4; j++) {
            const float v = e[j];
            if (v > m) { ssum = ssum * __expf(m - v) + 1.f; m = v; }
            else       { ssum += __expf(v - m); }
        }
    }
#pragma unroll
    for (int off = 16; off > 0; off >>= 1) {
        const float mo = __shfl_xor_sync(0xffffffffu, m, off);
        const float so = __shfl_xor_sync(0xffffffffu, ssum, off);
        const float mn = fmaxf(m, mo);
        ssum = ssum * __expf(m - mn) + so * __expf(mo - mn);
        m = mn;
    }
    const int wid = tid >> 5, lane = tid & 31;
    if (lane == 0) { red_m[wid] = m; red_s[wid] = ssum; }
    __syncthreads();   // also orders scatter atomics
    if (wid == 0) {
        float m2 = red_m[lane];
        float s2 = red_s[lane];
#pragma unroll
        for (int off = 16; off > 0; off >>= 1) {
            const float mo = __shfl_xor_sync(0xffffffffu, m2, off);
            const float so = __shfl_xor_sync(0xffffffffu, s2, off);
            const float mn = fmaxf(m2, mo);
            s2 = s2 * __expf(m2 - mn) + so * __expf(mo - mn);
            m2 = mn;
        }
        if (lane == 0) { red_m[0] = m2; red_s[0] = s2; }
    }
    __syncthreads();

    const float logZ = red_m[0] + __logf(red_s[0]);
    const float pt = p_trans[bt];
    const float lom = __logf(1.f - pt) - logZ;

    float4* rowv_w = (float4*)row;
    for (int i = tid; i < VV / 4; i += 1024) {
        const float4 l = rowv_w[i];
        const float4 t = tsv[i];
        const float le[4] = {l.x, l.y, l.z, l.w};
        const float te[4] = {t.x, t.y, t.z, t.w};
        float oe[4];
#pragma unroll
        for (int j = 0; j < 4; j++) {
            if (te[j] == 0.f) oe[j] = lom + le[j];
            else oe[j] = __logf(fmaf(pt, te[j], (1.f - pt) * __expf(le[j] - logZ)));
        }
        rowv_w[i] = make_float4(oe[0], oe[1], oe[2], oe[3]);
    }
}

// ---------------- launch ----------------
extern "C" void kernel_launch(void* const* d_in, const int* in_sizes, int n_in,
                              void* d_out, int out_size) {
    const float* dec_out     = (const float*)d_in[0];
    const float* W           = (const float*)d_in[1];
    const float* bias        = (const float*)d_in[2];
    const float* weights     = (const float*)d_in[3];
    const float* p_trans     = (const float*)d_in[4];
    const float* trans_probs = (const float*)d_in[5];
    const float* probs       = (const float*)d_in[6];
    const int*   idxes       = (const int*)d_in[7];
    float* out = (float*)d_out;

    conv_a_kernel<<<(MMROWS * 128 + 255) / 256, 256>>>(dec_out);
    conv_b_kernel<<<(HH * (VV / 4) + 255) / 256, 256>>>(W);

    cudaFuncSetAttribute(nmt_gemm_mma, cudaFuncAttributeMaxDynamicSharedMemorySize, GEMM_SMEM);
    nmt_gemm_mma<<<dim3(VV / BN, MPAD / BM), 256, GEMM_SMEM>>>(bias, out);

    const int fin_smem = VV * sizeof(float);
    cudaFuncSetAttribute(nmt_finalize_kernel, cudaFuncAttributeMaxDynamicSharedMemorySize, fin_smem);
    nmt_finalize_kernel<<<MMROWS, 1024, fin_smem>>>(weights, p_trans, trans_probs, probs, idxes, out);
}

// round 6
// speedup vs baseline: 2.2351x; 1.0601x over previous
#include <cuda_runtime.h>
#include <cuda_fp16.h>
#include <cstdint>

// ---------------- problem constants ----------------
#define BB 8
#define TT 100
#define SS 400
#define KK 8
#define HH 512
#define VV 32000
#define MMROWS 800
#define MPAD 896

// fp16 operands (single GEMM, K=512)
__device__ __half d_A2[(size_t)MPAD * HH];     // 0.92 MB (pad rows stay zero-init)
__device__ __half d_B2[(size_t)HH * VV];       // 32.8 MB (fits in L2)
__device__ float  d_logZ[MMROWS];              // per-row log partition

static __device__ __forceinline__ uint32_t pack_h2(__half a, __half b) {
    return (uint32_t)__half_as_ushort(a) | ((uint32_t)__half_as_ushort(b) << 16);
}

// ---------------- conversion: A -> fp16 ----------------
__global__ __launch_bounds__(256)
void conv_a_kernel(const float* __restrict__ A) {
    const int idx = blockIdx.x * 256 + threadIdx.x;      // 800*128
    if (idx >= MMROWS * 128) return;
    const int row = idx >> 7;
    const int kq = idx & 127;
    const float4 v = *(const float4*)(A + (size_t)row * HH + kq * 4);
    uint2 p;
    p.x = pack_h2(__float2half_rn(v.x), __float2half_rn(v.y));
    p.y = pack_h2(__float2half_rn(v.z), __float2half_rn(v.w));
    *(uint2*)(d_A2 + (size_t)row * HH + kq * 4) = p;
}

// ---------------- conversion: W -> fp16 ----------------
__global__ __launch_bounds__(256)
void conv_b_kernel(const float* __restrict__ W) {
    const int idx = blockIdx.x * 256 + threadIdx.x;      // 512*8000
    if (idx >= HH * (VV / 4)) return;
    const float4 v = *(const float4*)(W + (size_t)idx * 4);
    uint2 p;
    p.x = pack_h2(__float2half_rn(v.x), __float2half_rn(v.y));
    p.y = pack_h2(__float2half_rn(v.z), __float2half_rn(v.w));
    *(uint2*)(d_B2 + (size_t)idx * 4) = p;
}

// ---------------- mma.sync GEMM ----------------
#define BM 128
#define BN 128
#define BK 32
#define STAGES 4
#define KTILES (HH / BK)             // 16
#define A_STRIDE 40                  // halves/row (32 + 8 pad) -> 80 B
#define B_STRIDE 136                 // halves/row (128 + 8 pad) -> 272 B
#define A_BYTES (BM * A_STRIDE * 2)  // 10240
#define B_BYTES (BK * B_STRIDE * 2)  // 8704
#define STAGE_BYTES (A_BYTES + B_BYTES)  // 18944
#define GEMM_SMEM (STAGES * STAGE_BYTES) // 75776

__device__ __forceinline__ uint32_t smem_u32(const void* p) {
    uint32_t a;
    asm("{ .reg .u64 t; cvta.to.shared.u64 t, %1; cvt.u32.u64 %0, t; }" : "=r"(a) : "l"(p));
    return a;
}
__device__ __forceinline__ void cp16(uint32_t dst, const void* src) {
    asm volatile("cp.async.cg.shared.global [%0], [%1], 16;" :: "r"(dst), "l"(src) : "memory");
}
__device__ __forceinline__ void cp_commit() {
    asm volatile("cp.async.commit_group;" ::: "memory");
}
__device__ __forceinline__ void cp_wait2() {
    asm volatile("cp.async.wait_group 2;" ::: "memory");
}
__device__ __forceinline__ void ldm_x4(uint32_t* r, uint32_t addr) {
    asm volatile("ldmatrix.sync.aligned.m8n8.x4.shared.b16 {%0,%1,%2,%3}, [%4];"
                 : "=r"(r[0]), "=r"(r[1]), "=r"(r[2]), "=r"(r[3]) : "r"(addr));
}
__device__ __forceinline__ void ldm_x4_t(uint32_t* r, uint32_t addr) {
    asm volatile("ldmatrix.sync.aligned.m8n8.x4.trans.shared.b16 {%0,%1,%2,%3}, [%4];"
                 : "=r"(r[0]), "=r"(r[1]), "=r"(r[2]), "=r"(r[3]) : "r"(addr));
}
__device__ __forceinline__ void mma16816(float* c, const uint32_t* a, uint32_t b0, uint32_t b1) {
    asm volatile(
        "mma.sync.aligned.m16n8k16.row.col.f32.f16.f16.f32 "
        "{%0,%1,%2,%3}, {%4,%5,%6,%7}, {%8,%9}, {%0,%1,%2,%3};"
        : "+f"(c[0]), "+f"(c[1]), "+f"(c[2]), "+f"(c[3])
        : "r"(a[0]), "r"(a[1]), "r"(a[2]), "r"(a[3]), "r"(b0), "r"(b1));
}

__global__ __launch_bounds__(256)
void nmt_gemm_mma(const float* __restrict__ bias, float* __restrict__ C) {
    extern __shared__ char sm[];
    const uint32_t sm_base = smem_u32(sm);
    const int tid = threadIdx.x;
    const int warp = tid >> 5, lane = tid & 31;
    const int warp_m = warp >> 2;
    const int warp_n = warp & 3;
    const int nt = blockIdx.x;
    const int mt = blockIdx.y;

    const __half* Ag = d_A2 + (size_t)mt * BM * HH;
    const __half* Bg = d_B2 + (size_t)nt * BN;

    const int a_row0 = tid >> 2;
    const int a_q = tid & 3;
    const int b_row0 = tid >> 4;
    const int b_q = tid & 15;

    float acc[4][4][4];
#pragma unroll
    for (int t = 0; t < 4; t++)
#pragma unroll
        for (int n = 0; n < 4; n++)
#pragma unroll
            for (int j = 0; j < 4; j++) acc[t][n][j] = 0.f;

    auto load_stage = [&](int s, int kb) {
        const uint32_t as = sm_base + s * STAGE_BYTES;
        const uint32_t bs = as + A_BYTES;
#pragma unroll
        for (int j = 0; j < 2; j++) {
            const int row = a_row0 + j * 64;
            cp16(as + row * 80 + a_q * 16,
                 Ag + (size_t)row * HH + kb * BK + a_q * 8);
        }
#pragma unroll
        for (int j = 0; j < 2; j++) {
            const int row = b_row0 + j * 16;
            cp16(bs + row * 272 + b_q * 16,
                 Bg + (size_t)(kb * BK + row) * VV + b_q * 8);
        }
    };

#pragma unroll
    for (int s = 0; s < STAGES - 1; s++) { load_stage(s, s); cp_commit(); }

    for (int it = 0; it < KTILES; it++) {
        cp_wait2();
        __syncthreads();
        if (it + STAGES - 1 < KTILES) load_stage((it + STAGES - 1) & (STAGES - 1), it + STAGES - 1);
        cp_commit();

        const uint32_t as = sm_base + (it & (STAGES - 1)) * STAGE_BYTES;
        const uint32_t bs = as + A_BYTES;
#pragma unroll
        for (int k2 = 0; k2 < 2; k2++) {
            uint32_t af[4][4];
#pragma unroll
            for (int t = 0; t < 4; t++)
                ldm_x4(af[t], as + (warp_m * 64 + t * 16 + (lane & 15)) * 80
                              + k2 * 32 + (lane >> 4) * 16);
            uint32_t bf[2][4];
#pragma unroll
            for (int p = 0; p < 2; p++)
                ldm_x4_t(bf[p], bs + (k2 * 16 + (lane & 15)) * 272
                               + (warp_n * 32 + p * 16 + (lane >> 4) * 8) * 2);
#pragma unroll
            for (int t = 0; t < 4; t++)
#pragma unroll
                for (int n = 0; n < 4; n++)
                    mma16816(acc[t][n], af[t], bf[n >> 1][(n & 1) * 2], bf[n >> 1][(n & 1) * 2 + 1]);
        }
    }

    const int group = lane >> 2, tg = lane & 3;
#pragma unroll
    for (int t = 0; t < 4; t++) {
        const int r0 = mt * BM + warp_m * 64 + t * 16 + group;
        const int r1 = r0 + 8;
#pragma unroll
        for (int n = 0; n < 4; n++) {
            const int col = nt * BN + warp_n * 32 + n * 8 + tg * 2;
            const float2 bv = *(const float2*)(bias + col);
            if (r0 < MMROWS) {
                float2 o; o.x = acc[t][n][0] + bv.x; o.y = acc[t][n][1] + bv.y;
                *(float2*)(C + (size_t)r0 * VV + col) = o;
            }
            if (r1 < MMROWS) {
                float2 o; o.x = acc[t][n][2] + bv.x; o.y = acc[t][n][3] + bv.y;
                *(float2*)(C + (size_t)r1 * VV + col) = o;
            }
        }
    }
}

// ---------------- logZ reduction: one CTA per row, high occupancy ----------------
__global__ __launch_bounds__(256)
void nmt_logz_kernel(const float* __restrict__ out) {
    __shared__ float red_m[8];
    __shared__ float red_s[8];
    const int bt = blockIdx.x;
    const int tid = threadIdx.x;
    const float4* rowv = (const float4*)(out + (size_t)bt * VV);

    float m = -1e30f, ssum = 0.f;
    for (int i = tid; i < VV / 4; i += 256) {
        const float4 l = rowv[i];
        const float e[4] = {l.x, l.y, l.z, l.w};
#pragma unroll
        for (int j = 0; j < 4; j++) {
            const float v = e[j];
            if (v > m) { ssum = ssum * __expf(m - v) + 1.f; m = v; }
            else       { ssum += __expf(v - m); }
        }
    }
#pragma unroll
    for (int off = 16; off > 0; off >>= 1) {
        const float mo = __shfl_xor_sync(0xffffffffu, m, off);
        const float so = __shfl_xor_sync(0xffffffffu, ssum, off);
        const float mn = fmaxf(m, mo);
        ssum = ssum * __expf(m - mn) + so * __expf(mo - mn);
        m = mn;
    }
    const int wid = tid >> 5, lane = tid & 31;
    if (lane == 0) { red_m[wid] = m; red_s[wid] = ssum; }
    __syncthreads();
    if (wid == 0 && lane < 8) {
        float m2 = red_m[lane];
        float s2 = red_s[lane];
#pragma unroll
        for (int off = 4; off > 0; off >>= 1) {
            const float mo = __shfl_xor_sync(0xffu, m2, off);
            const float so = __shfl_xor_sync(0xffu, s2, off);
            const float mn = fmaxf(m2, mo);
            s2 = s2 * __expf(m2 - mn) + so * __expf(mo - mn);
            m2 = mn;
        }
        if (lane == 0) d_logZ[bt] = m2 + __logf(s2);
    }
}

// ---------------- blend: half-vocab per CTA (64KB smem -> 3 CTAs/SM) ----------------
#define VHALF (VV / 2)
__global__ __launch_bounds__(512)
void nmt_blend_kernel(const float* __restrict__ weights,
                      const float* __restrict__ p_trans,
                      const float* __restrict__ trans_probs,
                      const float* __restrict__ probs,
                      const int* __restrict__ idxes,
                      float* __restrict__ out) {
    extern __shared__ float ts[];               // VHALF floats (64 KB)
    const int half = blockIdx.x;                // 0..1
    const int bt = blockIdx.y;                  // 0..799
    const int b = bt / TT;
    const int tid = threadIdx.x;
    const int vbase = half * VHALF;

    float4* tsv = (float4*)ts;
    const float4 z4 = make_float4(0.f, 0.f, 0.f, 0.f);
    for (int i = tid; i < VHALF / 4; i += 512) tsv[i] = z4;
    __syncthreads();

    const float* wrow = weights + (size_t)bt * SS;
    const float* pb   = probs + (size_t)b * SS * KK;
    const float* tpb  = trans_probs + (size_t)b * SS * KK;
    const int* ib     = idxes + (size_t)b * SS * KK;
    for (int i = tid; i < SS * KK; i += 512) {
        if (pb[i] > 0.05f) {
            const int v = ib[i] - vbase;
            if ((unsigned)v < (unsigned)VHALF)
                atomicAdd(&ts[v], tpb[i] * wrow[i >> 3]);
        }
    }
    __syncthreads();

    const float logZ = d_logZ[bt];
    const float pt = p_trans[bt];
    const float lom = __logf(1.f - pt) - logZ;

    float4* rowv = (float4*)(out + (size_t)bt * VV + vbase);
    for (int i = tid; i < VHALF / 4; i += 512) {
        const float4 l = rowv[i];
        const float4 t = tsv[i];
        const float le[4] = {l.x, l.y, l.z, l.w};
        const float te[4] = {t.x, t.y, t.z, t.w};
        float oe[4];
#pragma unroll
        for (int j = 0; j < 4; j++) {
            if (te[j] == 0.f) oe[j] = lom + le[j];
            else oe[j] = __logf(fmaf(pt, te[j], (1.f - pt) * __expf(le[j] - logZ)));
        }
        rowv[i] = make_float4(oe[0], oe[1], oe[2], oe[3]);
    }
}

// ---------------- launch ----------------
extern "C" void kernel_launch(void* const* d_in, const int* in_sizes, int n_in,
                              void* d_out, int out_size) {
    const float* dec_out     = (const float*)d_in[0];
    const float* W           = (const float*)d_in[1];
    const float* bias        = (const float*)d_in[2];
    const float* weights     = (const float*)d_in[3];
    const float* p_trans     = (const float*)d_in[4];
    const float* trans_probs = (const float*)d_in[5];
    const float* probs       = (const float*)d_in[6];
    const int*   idxes       = (const int*)d_in[7];
    float* out = (float*)d_out;

    conv_a_kernel<<<(MMROWS * 128 + 255) / 256, 256>>>(dec_out);
    conv_b_kernel<<<(HH * (VV / 4) + 255) / 256, 256>>>(W);

    cudaFuncSetAttribute(nmt_gemm_mma, cudaFuncAttributeMaxDynamicSharedMemorySize, GEMM_SMEM);
    nmt_gemm_mma<<<dim3(VV / BN, MPAD / BM), 256, GEMM_SMEM>>>(bias, out);

    nmt_logz_kernel<<<MMROWS, 256>>>(out);

    const int blend_smem = VHALF * sizeof(float);    // 64000
    cudaFuncSetAttribute(nmt_blend_kernel, cudaFuncAttributeMaxDynamicSharedMemorySize, blend_smem);
    nmt_blend_kernel<<<dim3(2, MMROWS), 512, blend_smem>>>(weights, p_trans, trans_probs,
                                                           probs, idxes, out);
}

// round 7
// speedup vs baseline: 3.1917x; 1.4280x over previous
#include <cuda_runtime.h>
#include <cuda_fp16.h>
#include <cstdint>

// ---------------- problem constants ----------------
#define BB 8
#define TT 100
#define SS 400
#define KK 8
#define HH 512
#define VV 32000
#define MMROWS 800
#define MPAD 896

// fp16 operands (single GEMM, K=512)
__device__ __half d_A2[(size_t)MPAD * HH];     // 0.92 MB (pad rows stay zero-init)
__device__ __half d_B2[(size_t)HH * VV];       // 32.8 MB (fits in L2)
__device__ float  d_sumexp[MMROWS];            // per-row sum of exp(logit)

static __device__ __forceinline__ uint32_t pack_h2(__half a, __half b) {
    return (uint32_t)__half_as_ushort(a) | ((uint32_t)__half_as_ushort(b) << 16);
}

// ---------------- zero the per-row accumulators ----------------
__global__ void zero_sumexp_kernel() {
    d_sumexp[blockIdx.x * 256 + threadIdx.x % 256] = 0.f;   // grid 4 x 256 > 800 guarded below
}
__global__ __launch_bounds__(256)
void zero_sumexp() {
    const int i = blockIdx.x * 256 + threadIdx.x;
    if (i < MMROWS) d_sumexp[i] = 0.f;
}

// ---------------- conversion: A -> fp16 ----------------
__global__ __launch_bounds__(256)
void conv_a_kernel(const float* __restrict__ A) {
    const int idx = blockIdx.x * 256 + threadIdx.x;      // 800*128
    if (idx >= MMROWS * 128) return;
    const int row = idx >> 7;
    const int kq = idx & 127;
    const float4 v = *(const float4*)(A + (size_t)row * HH + kq * 4);
    uint2 p;
    p.x = pack_h2(__float2half_rn(v.x), __float2half_rn(v.y));
    p.y = pack_h2(__float2half_rn(v.z), __float2half_rn(v.w));
    *(uint2*)(d_A2 + (size_t)row * HH + kq * 4) = p;
}

// ---------------- conversion: W -> fp16 ----------------
__global__ __launch_bounds__(256)
void conv_b_kernel(const float* __restrict__ W) {
    const int idx = blockIdx.x * 256 + threadIdx.x;      // 512*8000
    if (idx >= HH * (VV / 4)) return;
    const float4 v = *(const float4*)(W + (size_t)idx * 4);
    uint2 p;
    p.x = pack_h2(__float2half_rn(v.x), __float2half_rn(v.y));
    p.y = pack_h2(__float2half_rn(v.z), __float2half_rn(v.w));
    *(uint2*)(d_B2 + (size_t)idx * 4) = p;
}

// ---------------- mma.sync GEMM + fused row-sumexp ----------------
#define BM 128
#define BN 128
#define BK 32
#define STAGES 4
#define KTILES (HH / BK)             // 16
#define A_STRIDE 40                  // halves/row (32 + 8 pad) -> 80 B
#define B_STRIDE 136                 // halves/row (128 + 8 pad) -> 272 B
#define A_BYTES (BM * A_STRIDE * 2)  // 10240
#define B_BYTES (BK * B_STRIDE * 2)  // 8704
#define STAGE_BYTES (A_BYTES + B_BYTES)  // 18944
#define GEMM_SMEM (STAGES * STAGE_BYTES) // 75776

__device__ __forceinline__ uint32_t smem_u32(const void* p) {
    uint32_t a;
    asm("{ .reg .u64 t; cvta.to.shared.u64 t, %1; cvt.u32.u64 %0, t; }" : "=r"(a) : "l"(p));
    return a;
}
__device__ __forceinline__ void cp16(uint32_t dst, const void* src) {
    asm volatile("cp.async.cg.shared.global [%0], [%1], 16;" :: "r"(dst), "l"(src) : "memory");
}
__device__ __forceinline__ void cp_commit() {
    asm volatile("cp.async.commit_group;" ::: "memory");
}
__device__ __forceinline__ void cp_wait2() {
    asm volatile("cp.async.wait_group 2;" ::: "memory");
}
__device__ __forceinline__ void ldm_x4(uint32_t* r, uint32_t addr) {
    asm volatile("ldmatrix.sync.aligned.m8n8.x4.shared.b16 {%0,%1,%2,%3}, [%4];"
                 : "=r"(r[0]), "=r"(r[1]), "=r"(r[2]), "=r"(r[3]) : "r"(addr));
}
__device__ __forceinline__ void ldm_x4_t(uint32_t* r, uint32_t addr) {
    asm volatile("ldmatrix.sync.aligned.m8n8.x4.trans.shared.b16 {%0,%1,%2,%3}, [%4];"
                 : "=r"(r[0]), "=r"(r[1]), "=r"(r[2]), "=r"(r[3]) : "r"(addr));
}
__device__ __forceinline__ void mma16816(float* c, const uint32_t* a, uint32_t b0, uint32_t b1) {
    asm volatile(
        "mma.sync.aligned.m16n8k16.row.col.f32.f16.f16.f32 "
        "{%0,%1,%2,%3}, {%4,%5,%6,%7}, {%8,%9}, {%0,%1,%2,%3};"
        : "+f"(c[0]), "+f"(c[1]), "+f"(c[2]), "+f"(c[3])
        : "r"(a[0]), "r"(a[1]), "r"(a[2]), "r"(a[3]), "r"(b0), "r"(b1));
}

__global__ __launch_bounds__(256)
void nmt_gemm_mma(const float* __restrict__ bias, float* __restrict__ C) {
    extern __shared__ char sm[];
    __shared__ float rowsum[BM];
    const uint32_t sm_base = smem_u32(sm);
    const int tid = threadIdx.x;
    const int warp = tid >> 5, lane = tid & 31;
    const int warp_m = warp >> 2;
    const int warp_n = warp & 3;
    const int nt = blockIdx.x;
    const int mt = blockIdx.y;

    const __half* Ag = d_A2 + (size_t)mt * BM * HH;
    const __half* Bg = d_B2 + (size_t)nt * BN;

    const int a_row0 = tid >> 2;
    const int a_q = tid & 3;
    const int b_row0 = tid >> 4;
    const int b_q = tid & 15;

    if (tid < BM) rowsum[tid] = 0.f;

    float acc[4][4][4];
#pragma unroll
    for (int t = 0; t < 4; t++)
#pragma unroll
        for (int n = 0; n < 4; n++)
#pragma unroll
            for (int j = 0; j < 4; j++) acc[t][n][j] = 0.f;

    auto load_stage = [&](int s, int kb) {
        const uint32_t as = sm_base + s * STAGE_BYTES;
        const uint32_t bs = as + A_BYTES;
#pragma unroll
        for (int j = 0; j < 2; j++) {
            const int row = a_row0 + j * 64;
            cp16(as + row * 80 + a_q * 16,
                 Ag + (size_t)row * HH + kb * BK + a_q * 8);
        }
#pragma unroll
        for (int j = 0; j < 2; j++) {
            const int row = b_row0 + j * 16;
            cp16(bs + row * 272 + b_q * 16,
                 Bg + (size_t)(kb * BK + row) * VV + b_q * 8);
        }
    };

#pragma unroll
    for (int s = 0; s < STAGES - 1; s++) { load_stage(s, s); cp_commit(); }

    for (int it = 0; it < KTILES; it++) {
        cp_wait2();
        __syncthreads();
        if (it + STAGES - 1 < KTILES) load_stage((it + STAGES - 1) & (STAGES - 1), it + STAGES - 1);
        cp_commit();

        const uint32_t as = sm_base + (it & (STAGES - 1)) * STAGE_BYTES;
        const uint32_t bs = as + A_BYTES;
#pragma unroll
        for (int k2 = 0; k2 < 2; k2++) {
            uint32_t af[4][4];
#pragma unroll
            for (int t = 0; t < 4; t++)
                ldm_x4(af[t], as + (warp_m * 64 + t * 16 + (lane & 15)) * 80
                              + k2 * 32 + (lane >> 4) * 16);
            uint32_t bf[2][4];
#pragma unroll
            for (int p = 0; p < 2; p++)
                ldm_x4_t(bf[p], bs + (k2 * 16 + (lane & 15)) * 272
                               + (warp_n * 32 + p * 16 + (lane >> 4) * 8) * 2);
#pragma unroll
            for (int t = 0; t < 4; t++)
#pragma unroll
                for (int n = 0; n < 4; n++)
                    mma16816(acc[t][n], af[t], bf[n >> 1][(n & 1) * 2], bf[n >> 1][(n & 1) * 2 + 1]);
        }
    }

    // epilogue: add bias, store logits, and fuse per-row sum(exp(logit))
    const int group = lane >> 2, tg = lane & 3;
#pragma unroll
    for (int t = 0; t < 4; t++) {
        const int lr0 = warp_m * 64 + t * 16 + group;   // local rows
        const int lr1 = lr0 + 8;
        const int r0 = mt * BM + lr0;
        const int r1 = mt * BM + lr1;
        float s0 = 0.f, s1 = 0.f;
#pragma unroll
        for (int n = 0; n < 4; n++) {
            const int col = nt * BN + warp_n * 32 + n * 8 + tg * 2;
            const float2 bv = *(const float2*)(bias + col);
            const float v00 = acc[t][n][0] + bv.x, v01 = acc[t][n][1] + bv.y;
            const float v10 = acc[t][n][2] + bv.x, v11 = acc[t][n][3] + bv.y;
            if (r0 < MMROWS) *(float2*)(C + (size_t)r0 * VV + col) = make_float2(v00, v01);
            if (r1 < MMROWS) *(float2*)(C + (size_t)r1 * VV + col) = make_float2(v10, v11);
            s0 += __expf(v00) + __expf(v01);
            s1 += __expf(v10) + __expf(v11);
        }
        atomicAdd(&rowsum[lr0], s0);
        atomicAdd(&rowsum[lr1], s1);
    }
    __syncthreads();
    if (tid < BM) {
        const int r = mt * BM + tid;
        if (r < MMROWS) atomicAdd(&d_sumexp[r], rowsum[tid]);
    }
}

// ---------------- blend: half-vocab per CTA (64KB smem -> 3 CTAs/SM) ----------------
#define VHALF (VV / 2)
__global__ __launch_bounds__(512)
void nmt_blend_kernel(const float* __restrict__ weights,
                      const float* __restrict__ p_trans,
                      const float* __restrict__ trans_probs,
                      const float* __restrict__ probs,
                      const int* __restrict__ idxes,
                      float* __restrict__ out) {
    extern __shared__ float ts[];               // VHALF floats (64 KB)
    const int half = blockIdx.x;                // 0..1
    const int bt = blockIdx.y;                  // 0..799
    const int b = bt / TT;
    const int tid = threadIdx.x;
    const int vbase = half * VHALF;

    float4* tsv = (float4*)ts;
    const float4 z4 = make_float4(0.f, 0.f, 0.f, 0.f);
    for (int i = tid; i < VHALF / 4; i += 512) tsv[i] = z4;
    __syncthreads();

    const float* wrow = weights + (size_t)bt * SS;
    const float* pb   = probs + (size_t)b * SS * KK;
    const float* tpb  = trans_probs + (size_t)b * SS * KK;
    const int* ib     = idxes + (size_t)b * SS * KK;
    for (int i = tid; i < SS * KK; i += 512) {
        if (pb[i] > 0.05f) {
            const int v = ib[i] - vbase;
            if ((unsigned)v < (unsigned)VHALF)
                atomicAdd(&ts[v], tpb[i] * wrow[i >> 3]);
        }
    }
    __syncthreads();

    const float logZ = __logf(d_sumexp[bt]);
    const float pt = p_trans[bt];
    const float lom = __logf(1.f - pt) - logZ;

    float4* rowv = (float4*)(out + (size_t)bt * VV + vbase);
    for (int i = tid; i < VHALF / 4; i += 512) {
        const float4 l = rowv[i];
        const float4 t = tsv[i];
        const float le[4] = {l.x, l.y, l.z, l.w};
        const float te[4] = {t.x, t.y, t.z, t.w};
        float oe[4];
#pragma unroll
        for (int j = 0; j < 4; j++) {
            if (te[j] == 0.f) oe[j] = lom + le[j];
            else oe[j] = __logf(fmaf(pt, te[j], (1.f - pt) * __expf(le[j] - logZ)));
        }
        rowv[i] = make_float4(oe[0], oe[1], oe[2], oe[3]);
    }
}

// ---------------- launch ----------------
extern "C" void kernel_launch(void* const* d_in, const int* in_sizes, int n_in,
                              void* d_out, int out_size) {
    const float* dec_out     = (const float*)d_in[0];
    const float* W           = (const float*)d_in[1];
    const float* bias        = (const float*)d_in[2];
    const float* weights     = (const float*)d_in[3];
    const float* p_trans     = (const float*)d_in[4];
    const float* trans_probs = (const float*)d_in[5];
    const float* probs       = (const float*)d_in[6];
    const int*   idxes       = (const int*)d_in[7];
    float* out = (float*)d_out;

    zero_sumexp<<<(MMROWS + 255) / 256, 256>>>();
    conv_a_kernel<<<(MMROWS * 128 + 255) / 256, 256>>>(dec_out);
    conv_b_kernel<<<(HH * (VV / 4) + 255) / 256, 256>>>(W);

    cudaFuncSetAttribute(nmt_gemm_mma, cudaFuncAttributeMaxDynamicSharedMemorySize, GEMM_SMEM);
    nmt_gemm_mma<<<dim3(VV / BN, MPAD / BM), 256, GEMM_SMEM>>>(bias, out);

    const int blend_smem = VHALF * sizeof(float);    // 64000
    cudaFuncSetAttribute(nmt_blend_kernel, cudaFuncAttributeMaxDynamicSharedMemorySize, blend_smem);
    nmt_blend_kernel<<<dim3(2, MMROWS), 512, blend_smem>>>(weights, p_trans, trans_probs,
                                                           probs, idxes, out);
}

// round 8
// speedup vs baseline: 3.5286x; 1.1056x over previous
#include <cuda_runtime.h>
#include <cuda_fp16.h>
#include <cstdint>

// ---------------- problem constants ----------------
#define BB 8
#define TT 100
#define SS 400
#define KK 8
#define HH 512
#define VV 32000
#define MMROWS 800
#define MPAD 896

// fp16 operands (single GEMM, K=512)
__device__ __half d_A2[(size_t)MPAD * HH];     // 0.92 MB (pad rows stay zero-init)
__device__ __half d_B2[(size_t)HH * VV];       // 32.8 MB (fits in L2)
__device__ float  d_sumexp[MMROWS];            // per-row sum of exp(logit)

static __device__ __forceinline__ uint32_t pack_h2(__half a, __half b) {
    return (uint32_t)__half_as_ushort(a) | ((uint32_t)__half_as_ushort(b) << 16);
}

__global__ __launch_bounds__(256)
void zero_sumexp() {
    const int i = blockIdx.x * 256 + threadIdx.x;
    if (i < MMROWS) d_sumexp[i] = 0.f;
}

// ---------------- conversion: A -> fp16 ----------------
__global__ __launch_bounds__(256)
void conv_a_kernel(const float* __restrict__ A) {
    const int idx = blockIdx.x * 256 + threadIdx.x;      // 800*128
    if (idx >= MMROWS * 128) return;
    const int row = idx >> 7;
    const int kq = idx & 127;
    const float4 v = *(const float4*)(A + (size_t)row * HH + kq * 4);
    uint2 p;
    p.x = pack_h2(__float2half_rn(v.x), __float2half_rn(v.y));
    p.y = pack_h2(__float2half_rn(v.z), __float2half_rn(v.w));
    *(uint2*)(d_A2 + (size_t)row * HH + kq * 4) = p;
}

// ---------------- conversion: W -> fp16 ----------------
__global__ __launch_bounds__(256)
void conv_b_kernel(const float* __restrict__ W) {
    const int idx = blockIdx.x * 256 + threadIdx.x;      // 512*8000
    if (idx >= HH * (VV / 4)) return;
    const float4 v = *(const float4*)(W + (size_t)idx * 4);
    uint2 p;
    p.x = pack_h2(__float2half_rn(v.x), __float2half_rn(v.y));
    p.y = pack_h2(__float2half_rn(v.z), __float2half_rn(v.w));
    *(uint2*)(d_B2 + (size_t)idx * 4) = p;
}

// ---------------- mma.sync GEMM + fused row-sumexp ----------------
// CTA 128x128, 128 threads = 4 warps (2x2), warp tile 64x64.
#define BM 128
#define BN 128
#define BK 32
#define STAGES 4
#define KTILES (HH / BK)             // 16
#define A_STRIDE 40                  // halves/row (32 + 8 pad) -> 80 B
#define B_STRIDE 136                 // halves/row (128 + 8 pad) -> 272 B
#define A_BYTES (BM * A_STRIDE * 2)  // 10240
#define B_BYTES (BK * B_STRIDE * 2)  // 8704
#define STAGE_BYTES (A_BYTES + B_BYTES)  // 18944
#define GEMM_SMEM (STAGES * STAGE_BYTES) // 75776

__device__ __forceinline__ uint32_t smem_u32(const void* p) {
    uint32_t a;
    asm("{ .reg .u64 t; cvta.to.shared.u64 t, %1; cvt.u32.u64 %0, t; }" : "=r"(a) : "l"(p));
    return a;
}
__device__ __forceinline__ void cp16(uint32_t dst, const void* src) {
    asm volatile("cp.async.cg.shared.global [%0], [%1], 16;" :: "r"(dst), "l"(src) : "memory");
}
__device__ __forceinline__ void cp_commit() {
    asm volatile("cp.async.commit_group;" ::: "memory");
}
__device__ __forceinline__ void cp_wait2() {
    asm volatile("cp.async.wait_group 2;" ::: "memory");
}
__device__ __forceinline__ void ldm_x4(uint32_t* r, uint32_t addr) {
    asm volatile("ldmatrix.sync.aligned.m8n8.x4.shared.b16 {%0,%1,%2,%3}, [%4];"
                 : "=r"(r[0]), "=r"(r[1]), "=r"(r[2]), "=r"(r[3]) : "r"(addr));
}
__device__ __forceinline__ void ldm_x4_t(uint32_t* r, uint32_t addr) {
    asm volatile("ldmatrix.sync.aligned.m8n8.x4.trans.shared.b16 {%0,%1,%2,%3}, [%4];"
                 : "=r"(r[0]), "=r"(r[1]), "=r"(r[2]), "=r"(r[3]) : "r"(addr));
}
__device__ __forceinline__ void mma16816(float* c, const uint32_t* a, uint32_t b0, uint32_t b1) {
    asm volatile(
        "mma.sync.aligned.m16n8k16.row.col.f32.f16.f16.f32 "
        "{%0,%1,%2,%3}, {%4,%5,%6,%7}, {%8,%9}, {%0,%1,%2,%3};"
        : "+f"(c[0]), "+f"(c[1]), "+f"(c[2]), "+f"(c[3])
        : "r"(a[0]), "r"(a[1]), "r"(a[2]), "r"(a[3]), "r"(b0), "r"(b1));
}

__global__ __launch_bounds__(128)
void nmt_gemm_mma(const float* __restrict__ bias, float* __restrict__ C) {
    extern __shared__ char sm[];
    __shared__ float rowsum[BM];
    const uint32_t sm_base = smem_u32(sm);
    const int tid = threadIdx.x;
    const int warp = tid >> 5, lane = tid & 31;
    const int warp_m = warp >> 1;        // 0..1 -> 64 rows
    const int warp_n = warp & 1;         // 0..1 -> 64 cols
    const int nt = blockIdx.x;
    const int mt = blockIdx.y;

    const __half* Ag = d_A2 + (size_t)mt * BM * HH;
    const __half* Bg = d_B2 + (size_t)nt * BN;

    // load mapping (128 threads): A 512 cp16 -> 4/thread; B 512 cp16 -> 4/thread
    const int a_row0 = tid >> 2;         // +32 steps
    const int a_q = tid & 3;             // 4 x 16B per 64B row
    const int b_row0 = tid >> 4;         // +8 steps
    const int b_q = tid & 15;

    if (tid < BM) rowsum[tid] = 0.f;

    float acc[4][8][4];
#pragma unroll
    for (int t = 0; t < 4; t++)
#pragma unroll
        for (int n = 0; n < 8; n++)
#pragma unroll
            for (int j = 0; j < 4; j++) acc[t][n][j] = 0.f;

    auto load_stage = [&](int s, int kb) {
        const uint32_t as = sm_base + s * STAGE_BYTES;
        const uint32_t bs = as + A_BYTES;
#pragma unroll
        for (int j = 0; j < 4; j++) {
            const int row = a_row0 + j * 32;
            cp16(as + row * 80 + a_q * 16,
                 Ag + (size_t)row * HH + kb * BK + a_q * 8);
        }
#pragma unroll
        for (int j = 0; j < 4; j++) {
            const int row = b_row0 + j * 8;
            cp16(bs + row * 272 + b_q * 16,
                 Bg + (size_t)(kb * BK + row) * VV + b_q * 8);
        }
    };

#pragma unroll
    for (int s = 0; s < STAGES - 1; s++) { load_stage(s, s); cp_commit(); }

    for (int it = 0; it < KTILES; it++) {
        cp_wait2();
        __syncthreads();
        if (it + STAGES - 1 < KTILES) load_stage((it + STAGES - 1) & (STAGES - 1), it + STAGES - 1);
        cp_commit();

        const uint32_t as = sm_base + (it & (STAGES - 1)) * STAGE_BYTES;
        const uint32_t bs = as + A_BYTES;
#pragma unroll
        for (int k2 = 0; k2 < 2; k2++) {
            uint32_t af[4][4];
#pragma unroll
            for (int t = 0; t < 4; t++)
                ldm_x4(af[t], as + (warp_m * 64 + t * 16 + (lane & 15)) * 80
                              + k2 * 32 + (lane >> 4) * 16);
            uint32_t bf[4][4];
#pragma unroll
            for (int p = 0; p < 4; p++)
                ldm_x4_t(bf[p], bs + (k2 * 16 + (lane & 15)) * 272
                               + (warp_n * 64 + p * 16 + (lane >> 4) * 8) * 2);
#pragma unroll
            for (int t = 0; t < 4; t++)
#pragma unroll
                for (int n = 0; n < 8; n++)
                    mma16816(acc[t][n], af[t], bf[n >> 1][(n & 1) * 2], bf[n >> 1][(n & 1) * 2 + 1]);
        }
    }

    // epilogue: add bias, store logits, fuse per-row sum(exp(logit))
    const int group = lane >> 2, tg = lane & 3;
#pragma unroll
    for (int t = 0; t < 4; t++) {
        const int lr0 = warp_m * 64 + t * 16 + group;
        const int lr1 = lr0 + 8;
        const int r0 = mt * BM + lr0;
        const int r1 = mt * BM + lr1;
        float s0 = 0.f, s1 = 0.f;
#pragma unroll
        for (int n = 0; n < 8; n++) {
            const int col = nt * BN + warp_n * 64 + n * 8 + tg * 2;
            const float2 bv = *(const float2*)(bias + col);
            const float v00 = acc[t][n][0] + bv.x, v01 = acc[t][n][1] + bv.y;
            const float v10 = acc[t][n][2] + bv.x, v11 = acc[t][n][3] + bv.y;
            if (r0 < MMROWS) *(float2*)(C + (size_t)r0 * VV + col) = make_float2(v00, v01);
            if (r1 < MMROWS) *(float2*)(C + (size_t)r1 * VV + col) = make_float2(v10, v11);
            s0 += __expf(v00) + __expf(v01);
            s1 += __expf(v10) + __expf(v11);
        }
        atomicAdd(&rowsum[lr0], s0);
        atomicAdd(&rowsum[lr1], s1);
    }
    __syncthreads();
    if (tid < BM) {
        const int r = mt * BM + tid;
        if (r < MMROWS) atomicAdd(&d_sumexp[r], rowsum[tid]);
    }
}

// ---------------- blend: half-vocab per CTA (64KB smem -> 3 CTAs/SM) ----------------
#define VHALF (VV / 2)
__global__ __launch_bounds__(512)
void nmt_blend_kernel(const float* __restrict__ weights,
                      const float* __restrict__ p_trans,
                      const float* __restrict__ trans_probs,
                      const float* __restrict__ probs,
                      const int* __restrict__ idxes,
                      float* __restrict__ out) {
    extern __shared__ float ts[];               // VHALF floats (64 KB)
    const int half = blockIdx.x;                // 0..1
    const int bt = blockIdx.y;                  // 0..799
    const int b = bt / TT;
    const int tid = threadIdx.x;
    const int vbase = half * VHALF;

    float4* tsv = (float4*)ts;
    const float4 z4 = make_float4(0.f, 0.f, 0.f, 0.f);
    for (int i = tid; i < VHALF / 4; i += 512) tsv[i] = z4;
    __syncthreads();

    const float* wrow = weights + (size_t)bt * SS;
    const float* pb   = probs + (size_t)b * SS * KK;
    const float* tpb  = trans_probs + (size_t)b * SS * KK;
    const int* ib     = idxes + (size_t)b * SS * KK;
    for (int i = tid; i < SS * KK; i += 512) {
        if (pb[i] > 0.05f) {
            const int v = ib[i] - vbase;
            if ((unsigned)v < (unsigned)VHALF)
                atomicAdd(&ts[v], tpb[i] * wrow[i >> 3]);
        }
    }
    __syncthreads();

    const float logZ = __logf(d_sumexp[bt]);
    const float pt = p_trans[bt];
    const float lom = __logf(1.f - pt) - logZ;

    float4* rowv = (float4*)(out + (size_t)bt * VV + vbase);
    for (int i = tid; i < VHALF / 4; i += 512) {
        const float4 l = rowv[i];
        const float4 t = tsv[i];
        const float le[4] = {l.x, l.y, l.z, l.w};
        const float te[4] = {t.x, t.y, t.z, t.w};
        float oe[4];
#pragma unroll
        for (int j = 0; j < 4; j++) {
            if (te[j] == 0.f) oe[j] = lom + le[j];
            else oe[j] = __logf(fmaf(pt, te[j], (1.f - pt) * __expf(le[j] - logZ)));
        }
        rowv[i] = make_float4(oe[0], oe[1], oe[2], oe[3]);
    }
}

// ---------------- launch ----------------
extern "C" void kernel_launch(void* const* d_in, const int* in_sizes, int n_in,
                              void* d_out, int out_size) {
    const float* dec_out     = (const float*)d_in[0];
    const float* W           = (const float*)d_in[1];
    const float* bias        = (const float*)d_in[2];
    const float* weights     = (const float*)d_in[3];
    const float* p_trans     = (const float*)d_in[4];
    const float* trans_probs = (const float*)d_in[5];
    const float* probs       = (const float*)d_in[6];
    const int*   idxes       = (const int*)d_in[7];
    float* out = (float*)d_out;

    zero_sumexp<<<(MMROWS + 255) / 256, 256>>>();
    conv_a_kernel<<<(MMROWS * 128 + 255) / 256, 256>>>(dec_out);
    conv_b_kernel<<<(HH * (VV / 4) + 255) / 256, 256>>>(W);

    cudaFuncSetAttribute(nmt_gemm_mma, cudaFuncAttributeMaxDynamicSharedMemorySize, GEMM_SMEM);
    nmt_gemm_mma<<<dim3(VV / BN, MPAD / BM), 128, GEMM_SMEM>>>(bias, out);

    const int blend_smem = VHALF * sizeof(float);    // 64000
    cudaFuncSetAttribute(nmt_blend_kernel, cudaFuncAttributeMaxDynamicSharedMemorySize, blend_smem);
    nmt_blend_kernel<<<dim3(2, MMROWS), 512, blend_smem>>>(weights, p_trans, trans_probs,
                                                           probs, idxes, out);
}